// round 16
// baseline (speedup 1.0000x reference)
#include <cuda_runtime.h>
#include <cuda_bf16.h>
#include <math.h>
#include <stdint.h>

// ---------------- problem constants ----------------
#define BB   8
#define NN   2048
#define HH   12
#define DD   768
#define DH   64
#define MF   256
#define TT   16384            // B*N tokens
#define RR   196608           // B*H*N head-rows
#define NBH  96               // B*H

// ---------------- fp32 scratch ----------------
__device__ float g_kp[RR * MF];          // raw xp (k only)
__device__ float g_diag[2 * RR];
__device__ float g_rmax[RR];             // per-row max of raw xp (k only)
__device__ float g_kmax[NBH];
__device__ float g_ksum[NBH * MF];
__device__ float g_dinv[RR];
__device__ float g_bqkv[3 * DD];

// ---------------- bf16 split scratch ----------------
__device__ __nv_bfloat16 g_xhi[TT * DD],  g_xlo[TT * DD];
__device__ __nv_bfloat16 g_wqkv_hi[3 * DD * DD], g_wqkv_lo[3 * DD * DD];
__device__ __nv_bfloat16 g_wo_hi[DD * DD], g_wo_lo[DD * DD];
__device__ __nv_bfloat16 g_proj_hi[MF * DH], g_proj_lo[MF * DH];
__device__ __nv_bfloat16 g_qhi[RR * DH], g_qlo[RR * DH];
__device__ __nv_bfloat16 g_khi[RR * DH], g_klo[RR * DH];
__device__ __nv_bfloat16 g_vhi[RR * DH], g_vlo[RR * DH];
__device__ __nv_bfloat16 g_ahi[TT * DD], g_alo[TT * DD];
__device__ __nv_bfloat16 g_qp_h[RR * MF], g_qp_l[RR * MF];   // phi(q) split
__device__ __nv_bfloat16 g_kp_h[RR * MF], g_kp_l[RR * MF];   // phi(k) split
__device__ __nv_bfloat16 g_ctx_h[NBH * MF * DH], g_ctx_l[NBH * MF * DH];

// =====================================================================
// helpers (base-ISA only: ldmatrix / mma.sync / cp.async)
// =====================================================================
__device__ __forceinline__ uint32_t smem_u32(const void* p) {
    uint32_t a;
    asm("{ .reg .u64 t; cvta.to.shared.u64 t, %1; cvt.u32.u64 %0, t; }" : "=r"(a) : "l"(p));
    return a;
}

#define LDSM4(r, addr) \
    asm volatile("ldmatrix.sync.aligned.m8n8.x4.shared.b16 {%0,%1,%2,%3}, [%4];" \
        : "=r"((r)[0]), "=r"((r)[1]), "=r"((r)[2]), "=r"((r)[3]) : "r"(addr))

#define LDSM4T(r, addr) \
    asm volatile("ldmatrix.sync.aligned.m8n8.x4.trans.shared.b16 {%0,%1,%2,%3}, [%4];" \
        : "=r"((r)[0]), "=r"((r)[1]), "=r"((r)[2]), "=r"((r)[3]) : "r"(addr))

#define MMA16816(c, a, b0, b1) \
    asm volatile("mma.sync.aligned.m16n8k16.row.col.f32.bf16.bf16.f32 " \
        "{%0,%1,%2,%3}, {%4,%5,%6,%7}, {%8,%9}, {%0,%1,%2,%3};" \
        : "+f"((c)[0]), "+f"((c)[1]), "+f"((c)[2]), "+f"((c)[3]) \
        : "r"((a)[0]), "r"((a)[1]), "r"((a)[2]), "r"((a)[3]), "r"(b0), "r"(b1))

#define CP_ASYNC16(saddr, gptr) \
    asm volatile("cp.async.cg.shared.global [%0], [%1], 16;" :: "r"(saddr), "l"(gptr))
#define CP_COMMIT() asm volatile("cp.async.commit_group;" ::: "memory")

// fast exp on the FMA pipe (no MUFU). Inputs <= ~0; underflow clamped.
__device__ __forceinline__ float fexp(float x) {
    float t = x * 1.4426950408889634f;
    float n = rintf(t);
    float f = t - n;
    float p = 1.54035303933816e-4f;
    p = fmaf(p, f, 1.33335581464284e-3f);
    p = fmaf(p, f, 9.61812910762848e-3f);
    p = fmaf(p, f, 5.55041086648216e-2f);
    p = fmaf(p, f, 2.40226506959101e-1f);
    p = fmaf(p, f, 6.93147180559945e-1f);
    p = fmaf(p, f, 1.0f);
    int ni = (int)n;
    ni = ni < -126 ? -126 : ni;
    float s = __int_as_float((uint32_t)(ni + 127) << 23);
    return p * s;
}

__device__ __forceinline__ void store_split2(__nv_bfloat16* hp, __nv_bfloat16* lp,
                                             size_t idx, float v0, float v1) {
    __nv_bfloat16 h0 = __float2bfloat16(v0), h1 = __float2bfloat16(v1);
    __nv_bfloat162 H; H.x = h0; H.y = h1;
    __nv_bfloat162 L;
    L.x = __float2bfloat16(v0 - __bfloat162float(h0));
    L.y = __float2bfloat16(v1 - __bfloat162float(h1));
    *(__nv_bfloat162*)(hp + idx) = H;
    *(__nv_bfloat162*)(lp + idx) = L;
}

// =====================================================================
// epilogue store for token-space GEMMs
// =====================================================================
template<int MODE>
__device__ __forceinline__ void store_pair(int t, int c, float v0, float v1,
                                           const float* __restrict__ bias,
                                           float* __restrict__ outp)
{
    if (MODE == 0) {
        int seg = c / DD; int oc = c - seg * DD;
        int h = oc >> 6, d0 = oc & 63;
        __nv_bfloat16 *oph, *opl;
        if (seg == 0)      { oph = g_qhi; opl = g_qlo; }
        else if (seg == 1) { oph = g_khi; opl = g_klo; }
        else               { oph = g_vhi; opl = g_vlo; }
        int bT = t >> 11, n = t & 2047;
        size_t base = (((size_t)(bT * HH + h)) * NN + n) * DH + d0;
        store_split2(oph, opl, base, v0 + g_bqkv[c], v1 + g_bqkv[c + 1]);
    } else {
        *(float2*)(outp + (size_t)t * DD + c) =
            make_float2(v0 + bias[c], v1 + bias[c + 1]);
    }
}

// =====================================================================
// split-fp32 HMMA GEMM for token-space projections (QKV / out-proj)
// =====================================================================
template<int MODE, int KD>
__global__ __launch_bounds__(256) void mma_gemm(const float* __restrict__ bias,
                                                float* __restrict__ outp)
{
    __shared__ __nv_bfloat16 shA[2 * 128 * 40];
    __shared__ __nv_bfloat16 shB[2 * 128 * 40];

    const int tid  = threadIdx.x;
    const int lane = tid & 31;
    const int wid  = tid >> 5;
    const int wm   = wid & 3;
    const int wn   = wid >> 2;
    const int row0 = blockIdx.y * 128;
    const int col0 = blockIdx.x * 128;

    const __nv_bfloat16 *Ahi, *Alo, *Bhi, *Blo;
    if (MODE == 0) { Ahi = g_xhi; Alo = g_xlo; Bhi = g_wqkv_hi; Blo = g_wqkv_lo; }
    else           { Ahi = g_ahi; Alo = g_alo; Bhi = g_wo_hi;   Blo = g_wo_lo;   }

    const uint32_t smA = smem_u32(shA);
    const uint32_t smB = smem_u32(shB);

    const int rowL  = tid >> 1;
    const int halfE = (tid & 1) * 16;

    const int numT = 3 * KD / 32;

#define LOAD_TILE(I, BUF) do {                                                   \
        int kcat = (I) * 32; int seg = kcat / KD; int koff = kcat - seg * KD;    \
        const __nv_bfloat16* Ap = (seg == 1) ? Alo : Ahi;                        \
        const __nv_bfloat16* Bp = (seg == 2) ? Blo : Bhi;                        \
        const __nv_bfloat16* ag = Ap + (size_t)(row0 + rowL) * KD + koff + halfE; \
        const __nv_bfloat16* bg = Bp + (size_t)(col0 + rowL) * KD + koff + halfE; \
        uint32_t sa  = smA + ((BUF) * 128 * 40 + rowL * 40 + halfE) * 2;         \
        uint32_t sbv = smB + ((BUF) * 128 * 40 + rowL * 40 + halfE) * 2;         \
        CP_ASYNC16(sa,       ag);                                                \
        CP_ASYNC16(sa  + 16, ag + 8);                                            \
        CP_ASYNC16(sbv,      bg);                                                \
        CP_ASYNC16(sbv + 16, bg + 8);                                            \
    } while (0)

    float c[2][8][4];
#pragma unroll
    for (int mf = 0; mf < 2; mf++)
#pragma unroll
        for (int nf = 0; nf < 8; nf++)
#pragma unroll
            for (int j = 0; j < 4; j++) c[mf][nf][j] = 0.f;

    LOAD_TILE(0, 0);
    CP_COMMIT();

    const int lrow = lane & 15;
    const int lcol = (lane >> 4) << 3;

    for (int i = 0; i < numT; i++) {
        if (i + 1 < numT) {
            LOAD_TILE(i + 1, (i + 1) & 1);
            CP_COMMIT();
            asm volatile("cp.async.wait_group 1;" ::: "memory");
        } else {
            asm volatile("cp.async.wait_group 0;" ::: "memory");
        }
        __syncthreads();

        const int buf = i & 1;
        const uint32_t baseA = smA + buf * (128 * 40 * 2);
        const uint32_t baseB = smB + buf * (128 * 40 * 2);

#pragma unroll
        for (int k16 = 0; k16 < 32; k16 += 16) {
            uint32_t a[2][4], bq[4][4];
#pragma unroll
            for (int mf = 0; mf < 2; mf++) {
                uint32_t ad = baseA + ((wm * 32 + mf * 16 + lrow) * 40 + k16 + lcol) * 2;
                LDSM4(a[mf], ad);
            }
#pragma unroll
            for (int nf4 = 0; nf4 < 4; nf4++) {
                uint32_t bd = baseB + ((wn * 64 + nf4 * 16 + lrow) * 40 + k16 + lcol) * 2;
                LDSM4(bq[nf4], bd);
            }
#pragma unroll
            for (int mf = 0; mf < 2; mf++)
#pragma unroll
                for (int nf4 = 0; nf4 < 4; nf4++) {
                    MMA16816(c[mf][nf4 * 2],     a[mf], bq[nf4][0], bq[nf4][2]);
                    MMA16816(c[mf][nf4 * 2 + 1], a[mf], bq[nf4][1], bq[nf4][3]);
                }
        }
        __syncthreads();
    }
#undef LOAD_TILE

    const int rowA = lane >> 2;
    const int colp = (lane & 3) * 2;
#pragma unroll
    for (int mf = 0; mf < 2; mf++)
#pragma unroll
        for (int nf = 0; nf < 8; nf++) {
            int m = row0 + wm * 32 + mf * 16 + rowA;
            int n = col0 + wn * 64 + nf * 8 + colp;
            store_pair<MODE>(m,     n, c[mf][nf][0], c[mf][nf][1], bias, outp);
            store_pair<MODE>(m + 8, n, c[mf][nf][2], c[mf][nf][3], bias, outp);
        }
}

// =====================================================================
// feat_mma: xp = dn * (q|k) @ proj^T over the FULL feature dim in one CTA.
// CTA tile 128(rows) x 256(features), 512 threads (16 warps, 4m x 4n),
// warp tile 32x64. 3-term split over K concat = 192 (6 tiles of 32).
// Epilogue computes per-row max in-CTA:
//   ISQ=1: fused poly-exp -> phi(q) hi/lo split store (no fp32 xp at all)
//   ISQ=0: stores raw xp fp32 (head max is global) + writes g_rmax
// =====================================================================
template<int ISQ>
__global__ __launch_bounds__(512) void feat_mma()
{
    extern __shared__ char dyn[];
    __nv_bfloat16* shA = (__nv_bfloat16*)dyn;                    // 2*128*40
    __nv_bfloat16* shB = (__nv_bfloat16*)(dyn + 20480);          // 2*256*40
    float* red         = (float*)(dyn + 20480 + 40960);          // 4*128

    const int tid = threadIdx.x, lane = tid & 31, wid = tid >> 5;
    const int wm = wid & 3, wn = wid >> 2;
    const int r0 = blockIdx.x * 128;

    const __nv_bfloat16* Ahi = ISQ ? g_qhi : g_khi;
    const __nv_bfloat16* Alo = ISQ ? g_qlo : g_klo;

    const uint32_t smA = smem_u32(shA);
    const uint32_t smB = smem_u32(shB);

    const int arow = tid >> 2, aq = tid & 3;       // A loader: 1 x 16B per thread
    const int brow = tid >> 1, bhalf = tid & 1;    // B loader: 2 x 16B per thread

    const int numT = 6;

#define F_LOAD(I, BUF) do {                                                      \
        int kc = (I) * 32; int seg = kc >> 6; int koff = kc - (seg << 6);        \
        const __nv_bfloat16* Ap = (seg == 1) ? Alo : Ahi;                        \
        const __nv_bfloat16* Bp = (seg == 2) ? g_proj_lo : g_proj_hi;            \
        const __nv_bfloat16* ag = Ap + (size_t)(r0 + arow) * DH + koff + aq * 8; \
        uint32_t sa = smA + ((BUF) * 128 * 40 + arow * 40 + aq * 8) * 2;         \
        CP_ASYNC16(sa, ag);                                                      \
        const __nv_bfloat16* bg = Bp + (size_t)brow * DH + koff + bhalf * 16;    \
        uint32_t sb = smB + ((BUF) * 256 * 40 + brow * 40 + bhalf * 16) * 2;     \
        CP_ASYNC16(sb,      bg);                                                 \
        CP_ASYNC16(sb + 16, bg + 8);                                             \
    } while (0)

    float c[2][8][4];
#pragma unroll
    for (int mf = 0; mf < 2; mf++)
#pragma unroll
        for (int nf = 0; nf < 8; nf++)
#pragma unroll
            for (int j = 0; j < 4; j++) c[mf][nf][j] = 0.f;

    F_LOAD(0, 0);
    CP_COMMIT();

    const int lrow = lane & 15;
    const int lcol = (lane >> 4) << 3;

    for (int i = 0; i < numT; i++) {
        if (i + 1 < numT) {
            F_LOAD(i + 1, (i + 1) & 1);
            CP_COMMIT();
            asm volatile("cp.async.wait_group 1;" ::: "memory");
        } else {
            asm volatile("cp.async.wait_group 0;" ::: "memory");
        }
        __syncthreads();

        const int buf = i & 1;
        const uint32_t baseA = smA + buf * (128 * 40 * 2);
        const uint32_t baseB = smB + buf * (256 * 40 * 2);

#pragma unroll
        for (int k16 = 0; k16 < 32; k16 += 16) {
            uint32_t a[2][4], bq[4][4];
#pragma unroll
            for (int mf = 0; mf < 2; mf++) {
                uint32_t ad = baseA + ((wm * 32 + mf * 16 + lrow) * 40 + k16 + lcol) * 2;
                LDSM4(a[mf], ad);
            }
#pragma unroll
            for (int nf4 = 0; nf4 < 4; nf4++) {
                uint32_t bd = baseB + ((wn * 64 + nf4 * 16 + lrow) * 40 + k16 + lcol) * 2;
                LDSM4(bq[nf4], bd);
            }
#pragma unroll
            for (int mf = 0; mf < 2; mf++)
#pragma unroll
                for (int nf4 = 0; nf4 < 4; nf4++) {
                    MMA16816(c[mf][nf4 * 2],     a[mf], bq[nf4][0], bq[nf4][2]);
                    MMA16816(c[mf][nf4 * 2 + 1], a[mf], bq[nf4][1], bq[nf4][3]);
                }
        }
        __syncthreads();
    }
#undef F_LOAD

    // scale by data_normalizer
    const float dnv = 0.35355339059327373f;
#pragma unroll
    for (int mf = 0; mf < 2; mf++)
#pragma unroll
        for (int nf = 0; nf < 8; nf++)
#pragma unroll
            for (int j = 0; j < 4; j++) c[mf][nf][j] *= dnv;

    // thread-local row max (lo = rows rowA, hi = rows rowA+8)
    float rmx[2][2];
#pragma unroll
    for (int mf = 0; mf < 2; mf++) {
        float lo = c[mf][0][0], hi = c[mf][0][2];
#pragma unroll
        for (int nf = 0; nf < 8; nf++) {
            lo = fmaxf(lo, fmaxf(c[mf][nf][0], c[mf][nf][1]));
            hi = fmaxf(hi, fmaxf(c[mf][nf][2], c[mf][nf][3]));
        }
        rmx[mf][0] = lo; rmx[mf][1] = hi;
    }
    // quad reduce (lanes sharing rowA)
#pragma unroll
    for (int o = 1; o <= 2; o <<= 1)
#pragma unroll
        for (int mf = 0; mf < 2; mf++) {
            rmx[mf][0] = fmaxf(rmx[mf][0], __shfl_xor_sync(0xffffffffu, rmx[mf][0], o));
            rmx[mf][1] = fmaxf(rmx[mf][1], __shfl_xor_sync(0xffffffffu, rmx[mf][1], o));
        }
    const int rowA = lane >> 2, colp = (lane & 3) * 2;
    if ((lane & 3) == 0) {
#pragma unroll
        for (int mf = 0; mf < 2; mf++) {
            red[wn * 128 + wm * 32 + mf * 16 + rowA]     = rmx[mf][0];
            red[wn * 128 + wm * 32 + mf * 16 + rowA + 8] = rmx[mf][1];
        }
    }
    __syncthreads();

#pragma unroll
    for (int mf = 0; mf < 2; mf++)
#pragma unroll
        for (int part = 0; part < 2; part++) {
            int rloc = wm * 32 + mf * 16 + rowA + part * 8;
            int r = r0 + rloc;
            float mrow = fmaxf(fmaxf(red[rloc], red[128 + rloc]),
                               fmaxf(red[256 + rloc], red[384 + rloc]));
            if (ISQ) {
                float sub = g_diag[r] + mrow;
#pragma unroll
                for (int nf = 0; nf < 8; nf++) {
                    int n = wn * 64 + nf * 8 + colp;
                    float v0 = c[mf][nf][part * 2],  v1 = c[mf][nf][part * 2 + 1];
                    float p0 = 0.0625f * (fexp(v0 - sub) + 1e-4f);
                    float p1 = 0.0625f * (fexp(v1 - sub) + 1e-4f);
                    store_split2(g_qp_h, g_qp_l, (size_t)r * MF + n, p0, p1);
                }
            } else {
#pragma unroll
                for (int nf = 0; nf < 8; nf++) {
                    int n = wn * 64 + nf * 8 + colp;
                    *(float2*)(g_kp + (size_t)r * MF + n) =
                        make_float2(c[mf][nf][part * 2], c[mf][nf][part * 2 + 1]);
                }
                if (wn == 0 && (lane & 3) == 0) g_rmax[r] = mrow;
            }
        }
}

// =====================================================================
// ctx HMMA (unchanged)
// =====================================================================
__global__ __launch_bounds__(256) void ctx_mma()
{
    __shared__ __nv_bfloat16 shA[2 * 32 * 136];
    __shared__ __nv_bfloat16 shV[2 * 32 * 72];

    const int tid = threadIdx.x, lane = tid & 31, wid = tid >> 5;
    const int wm = wid & 3, wn = wid >> 2;
    const int bh = blockIdx.y;
    const int m0 = blockIdx.x * 128;

    const __nv_bfloat16* kph = g_kp_h + (size_t)bh * NN * MF;
    const __nv_bfloat16* kpl = g_kp_l + (size_t)bh * NN * MF;
    const __nv_bfloat16* vhp = g_vhi + (size_t)bh * NN * DH;
    const __nv_bfloat16* vlp = g_vlo + (size_t)bh * NN * DH;

    const uint32_t smA = smem_u32(shA);
    const uint32_t smV = smem_u32(shV);

    const int arow = tid >> 3, achk = tid & 7;
    const int numT = 3 * NN / 32;

#define CTX_LOAD(I, BUF) do {                                                    \
        int kc = (I) * 32; int seg = kc / NN; int noff = kc - seg * NN;          \
        const __nv_bfloat16* Ap = (seg == 1) ? kpl : kph;                        \
        const __nv_bfloat16* Vp = (seg == 2) ? vlp : vhp;                        \
        const __nv_bfloat16* ag = Ap + (size_t)(noff + arow) * MF + m0 + achk * 8; \
        uint32_t sa = smA + ((BUF) * 32 * 136 + arow * 136 + achk * 8) * 2;      \
        CP_ASYNC16(sa,       ag);                                                \
        CP_ASYNC16(sa + 128, ag + 64);                                           \
        const __nv_bfloat16* vg = Vp + (size_t)(noff + arow) * DH + achk * 8;    \
        uint32_t sv = smV + ((BUF) * 32 * 72 + arow * 72 + achk * 8) * 2;        \
        CP_ASYNC16(sv, vg);                                                      \
    } while (0)

    float c[2][4][4];
#pragma unroll
    for (int mf = 0; mf < 2; mf++)
#pragma unroll
        for (int nf = 0; nf < 4; nf++)
#pragma unroll
            for (int j = 0; j < 4; j++) c[mf][nf][j] = 0.f;

    CTX_LOAD(0, 0);
    CP_COMMIT();

    const int trow = lane & 7;
    const int tm8  = ((lane >> 3) & 1) * 8;
    const int tk8  = ((lane >> 4) & 1) * 8;

    for (int i = 0; i < numT; i++) {
        if (i + 1 < numT) {
            CTX_LOAD(i + 1, (i + 1) & 1);
            CP_COMMIT();
            asm volatile("cp.async.wait_group 1;" ::: "memory");
        } else {
            asm volatile("cp.async.wait_group 0;" ::: "memory");
        }
        __syncthreads();

        const int buf = i & 1;
        const uint32_t baseA = smA + buf * (32 * 136 * 2);
        const uint32_t baseV = smV + buf * (32 * 72 * 2);

#pragma unroll
        for (int k16 = 0; k16 < 32; k16 += 16) {
            uint32_t a[2][4], bq[2][4];
#pragma unroll
            for (int mf = 0; mf < 2; mf++) {
                uint32_t ad = baseA + ((k16 + trow + tk8) * 136 + wm * 32 + mf * 16 + tm8) * 2;
                LDSM4T(a[mf], ad);
            }
#pragma unroll
            for (int nf = 0; nf < 2; nf++) {
                uint32_t bd = baseV + ((k16 + trow + tk8) * 72 + wn * 32 + nf * 16 + tm8) * 2;
                LDSM4T(bq[nf], bd);
            }
#pragma unroll
            for (int mf = 0; mf < 2; mf++)
#pragma unroll
                for (int nf = 0; nf < 2; nf++) {
                    MMA16816(c[mf][nf * 2],     a[mf], bq[nf][0], bq[nf][2]);
                    MMA16816(c[mf][nf * 2 + 1], a[mf], bq[nf][1], bq[nf][3]);
                }
        }
        __syncthreads();
    }
#undef CTX_LOAD

    const int rowA = lane >> 2, colp = (lane & 3) * 2;
#pragma unroll
    for (int mf = 0; mf < 2; mf++)
#pragma unroll
        for (int blk = 0; blk < 4; blk++) {
            int m = m0 + wm * 32 + mf * 16 + rowA;
            int d = wn * 32 + blk * 8 + colp;
            size_t b0 = ((size_t)bh * MF + m) * DH + d;
            store_split2(g_ctx_h, g_ctx_l, b0,          c[mf][blk][0], c[mf][blk][1]);
            store_split2(g_ctx_h, g_ctx_l, b0 + 8 * DH, c[mf][blk][2], c[mf][blk][3]);
        }
}

// =====================================================================
// outattn HMMA (unchanged)
// =====================================================================
__global__ __launch_bounds__(256) void outattn_mma()
{
    __shared__ __nv_bfloat16 shA[2 * 128 * 40];
    __shared__ __nv_bfloat16 shB[2 * 32 * 72];

    const int tid = threadIdx.x, lane = tid & 31, wid = tid >> 5;
    const int wm = wid & 3, wn = wid >> 2;
    const int r0 = blockIdx.x * 128;
    const int bh = r0 >> 11;

    const __nv_bfloat16* cth = g_ctx_h + (size_t)bh * MF * DH;
    const __nv_bfloat16* ctl = g_ctx_l + (size_t)bh * MF * DH;

    const uint32_t smA = smem_u32(shA);
    const uint32_t smB = smem_u32(shB);

    const int rowL = tid >> 1, halfE = (tid & 1) * 16;
    const int brow = tid >> 3, bchk = tid & 7;
    const int numT = 3 * MF / 32;

#define OA_LOAD(I, BUF) do {                                                     \
        int kc = (I) * 32; int seg = kc / MF; int moff = kc - seg * MF;          \
        const __nv_bfloat16* Ap = (seg == 1) ? g_qp_l : g_qp_h;                  \
        const __nv_bfloat16* Bp = (seg == 2) ? ctl : cth;                        \
        const __nv_bfloat16* ag = Ap + (size_t)(r0 + rowL) * MF + moff + halfE;  \
        uint32_t sa = smA + ((BUF) * 128 * 40 + rowL * 40 + halfE) * 2;          \
        CP_ASYNC16(sa,      ag);                                                 \
        CP_ASYNC16(sa + 16, ag + 8);                                             \
        const __nv_bfloat16* bg = Bp + (size_t)(moff + brow) * DH + bchk * 8;    \
        uint32_t sb = smB + ((BUF) * 32 * 72 + brow * 72 + bchk * 8) * 2;        \
        CP_ASYNC16(sb, bg);                                                      \
    } while (0)

    float c[2][4][4];
#pragma unroll
    for (int mf = 0; mf < 2; mf++)
#pragma unroll
        for (int nf = 0; nf < 4; nf++)
#pragma unroll
            for (int j = 0; j < 4; j++) c[mf][nf][j] = 0.f;

    OA_LOAD(0, 0);
    CP_COMMIT();

    const int lrow = lane & 15;
    const int lcol = (lane >> 4) << 3;
    const int trow = lane & 7;
    const int tm8  = ((lane >> 3) & 1) * 8;
    const int tk8  = ((lane >> 4) & 1) * 8;

    for (int i = 0; i < numT; i++) {
        if (i + 1 < numT) {
            OA_LOAD(i + 1, (i + 1) & 1);
            CP_COMMIT();
            asm volatile("cp.async.wait_group 1;" ::: "memory");
        } else {
            asm volatile("cp.async.wait_group 0;" ::: "memory");
        }
        __syncthreads();

        const int buf = i & 1;
        const uint32_t baseA = smA + buf * (128 * 40 * 2);
        const uint32_t baseB = smB + buf * (32 * 72 * 2);

#pragma unroll
        for (int k16 = 0; k16 < 32; k16 += 16) {
            uint32_t a[2][4], bq[2][4];
#pragma unroll
            for (int mf = 0; mf < 2; mf++) {
                uint32_t ad = baseA + ((wm * 32 + mf * 16 + lrow) * 40 + k16 + lcol) * 2;
                LDSM4(a[mf], ad);
            }
#pragma unroll
            for (int nf = 0; nf < 2; nf++) {
                uint32_t bd = baseB + ((k16 + trow + tk8) * 72 + wn * 32 + nf * 16 + tm8) * 2;
                LDSM4T(bq[nf], bd);
            }
#pragma unroll
            for (int mf = 0; mf < 2; mf++)
#pragma unroll
                for (int nf = 0; nf < 2; nf++) {
                    MMA16816(c[mf][nf * 2],     a[mf], bq[nf][0], bq[nf][2]);
                    MMA16816(c[mf][nf * 2 + 1], a[mf], bq[nf][1], bq[nf][3]);
                }
        }
        __syncthreads();
    }
#undef OA_LOAD

    const int rowA = lane >> 2, colp = (lane & 3) * 2;
    const int b = bh / HH, h = bh - b * HH;
#pragma unroll
    for (int mf = 0; mf < 2; mf++)
#pragma unroll
        for (int blk = 0; blk < 4; blk++) {
            int r = r0 + wm * 32 + mf * 16 + rowA;
            int d = wn * 32 + blk * 8 + colp;
            {
                float di = g_dinv[r];
                int t = b * NN + (r & 2047);
                store_split2(g_ahi, g_alo, (size_t)t * DD + h * DH + d,
                             c[mf][blk][0] * di, c[mf][blk][1] * di);
            }
            {
                int r2 = r + 8;
                float di = g_dinv[r2];
                int t = b * NN + (r2 & 2047);
                store_split2(g_ahi, g_alo, (size_t)t * DD + h * DH + d,
                             c[mf][blk][2] * di, c[mf][blk][3] * di);
            }
        }
}

// =====================================================================
// split helpers
// =====================================================================
__device__ __forceinline__ void split_vec(float4 v, __nv_bfloat162* h2,
                                          __nv_bfloat162* l2, size_t i4)
{
    __nv_bfloat16 a = __float2bfloat16(v.x), b = __float2bfloat16(v.y);
    __nv_bfloat16 c = __float2bfloat16(v.z), d = __float2bfloat16(v.w);
    __nv_bfloat162 H0, H1, L0, L1;
    H0.x = a; H0.y = b; H1.x = c; H1.y = d;
    L0.x = __float2bfloat16(v.x - __bfloat162float(a));
    L0.y = __float2bfloat16(v.y - __bfloat162float(b));
    L1.x = __float2bfloat16(v.z - __bfloat162float(c));
    L1.y = __float2bfloat16(v.w - __bfloat162float(d));
    h2[2 * i4] = H0; h2[2 * i4 + 1] = H1;
    l2[2 * i4] = L0; l2[2 * i4 + 1] = L1;
}

__global__ void split_x_kernel(const float* __restrict__ x) {
    size_t i = (size_t)blockIdx.x * 256 + threadIdx.x;
    split_vec(((const float4*)x)[i], (__nv_bfloat162*)g_xhi, (__nv_bfloat162*)g_xlo, i);
}
__global__ void split_wqkv_kernel(const float* __restrict__ Wq,
                                  const float* __restrict__ Wk,
                                  const float* __restrict__ Wv) {
    int z = blockIdx.y;
    const float* W = (z == 0) ? Wq : (z == 1) ? Wk : Wv;
    size_t i = (size_t)blockIdx.x * 256 + threadIdx.x;
    __nv_bfloat162* h = (__nv_bfloat162*)(g_wqkv_hi + (size_t)z * DD * DD);
    __nv_bfloat162* l = (__nv_bfloat162*)(g_wqkv_lo + (size_t)z * DD * DD);
    split_vec(((const float4*)W)[i], h, l, i);
}
__global__ void split_wo_kernel(const float* __restrict__ Wo) {
    size_t i = (size_t)blockIdx.x * 256 + threadIdx.x;
    split_vec(((const float4*)Wo)[i], (__nv_bfloat162*)g_wo_hi, (__nv_bfloat162*)g_wo_lo, i);
}
__global__ void split_proj_kernel(const float* __restrict__ p) {
    size_t i = (size_t)blockIdx.x * 256 + threadIdx.x;
    split_vec(((const float4*)p)[i], (__nv_bfloat162*)g_proj_hi, (__nv_bfloat162*)g_proj_lo, i);
}
__global__ void bias_cat_kernel(const float* __restrict__ bq,
                                const float* __restrict__ bk,
                                const float* __restrict__ bv) {
    int z = blockIdx.x;
    const float* b = (z == 0) ? bq : (z == 1) ? bk : bv;
    g_bqkv[z * DD + threadIdx.x] = b[threadIdx.x];
}

// =====================================================================
// small kernels
// =====================================================================
__global__ void diag_kernel()
{
    int z = blockIdx.y;
    const __nv_bfloat16* ph = (z ? g_khi : g_qhi);
    const __nv_bfloat16* pl = (z ? g_klo : g_qlo);
    int warp = threadIdx.x >> 5, lane = threadIdx.x & 31;
    int r = blockIdx.x * 8 + warp;
    size_t base = (size_t)r * DH;
    float a = __bfloat162float(ph[base + lane])      + __bfloat162float(pl[base + lane]);
    float b = __bfloat162float(ph[base + lane + 32]) + __bfloat162float(pl[base + lane + 32]);
    float s = a * a + b * b;
#pragma unroll
    for (int o = 16; o; o >>= 1) s += __shfl_xor_sync(0xffffffffu, s, o);
    if (lane == 0) g_diag[z * RR + r] = s * 0.0625f;
}

__global__ void kheadmax_kernel()
{
    int bh = blockIdx.x, tid = threadIdx.x;
    const float* p = g_rmax + (size_t)bh * NN;
    float mx = -1e30f;
    for (int i = tid; i < NN; i += 256) mx = fmaxf(mx, p[i]);
    __shared__ float sm[256];
    sm[tid] = mx;
    __syncthreads();
    for (int s = 128; s > 0; s >>= 1) {
        if (tid < s) sm[tid] = fmaxf(sm[tid], sm[tid + s]);
        __syncthreads();
    }
    if (tid == 0) g_kmax[bh] = sm[0];
    g_ksum[bh * MF + tid] = 0.f;
}

__global__ void kexp_kernel()
{
    int bh  = blockIdx.y;
    int m   = threadIdx.x;
    int r0  = bh * NN + blockIdx.x * 256;
    float headsub = g_kmax[bh];
    const float* diag = g_diag + RR;
    float acc = 0.f;
    for (int i = 0; i < 256; i++) {
        int r = r0 + i;
        size_t idx = (size_t)r * MF + m;
        float ph = 0.0625f * (fexp(g_kp[idx] - diag[r] - headsub) + 1e-4f);
        __nv_bfloat16 hh = __float2bfloat16(ph);
        g_kp_h[idx] = hh;
        g_kp_l[idx] = __float2bfloat16(ph - __bfloat162float(hh));
        acc += ph;
    }
    atomicAdd(&g_ksum[bh * MF + m], acc);
}

__global__ void dden_kernel()
{
    int warp = threadIdx.x >> 5, lane = threadIdx.x & 31;
    int r  = blockIdx.x * 8 + warp;
    int bh = r >> 11;
    const __nv_bfloat16* qh = g_qp_h + (size_t)r * MF;
    const __nv_bfloat16* ql = g_qp_l + (size_t)r * MF;
    const float* ks = g_ksum + bh * MF;
    float s = 0.f;
#pragma unroll
    for (int i = 0; i < 8; i++) {
        int j = lane + i * 32;
        float qv = __bfloat162float(qh[j]) + __bfloat162float(ql[j]);
        s += qv * ks[j];
    }
#pragma unroll
    for (int o = 16; o; o >>= 1) s += __shfl_xor_sync(0xffffffffu, s, o);
    if (lane == 0) g_dinv[r] = 1.f / s;
}

// =====================================================================
extern "C" void kernel_launch(void* const* d_in, const int* in_sizes, int n_in,
                              void* d_out, int out_size)
{
    const float* x    = (const float*)d_in[0];
    const float* Wq   = (const float*)d_in[1];
    const float* bq   = (const float*)d_in[2];
    const float* Wk   = (const float*)d_in[3];
    const float* bk   = (const float*)d_in[4];
    const float* Wv   = (const float*)d_in[5];
    const float* bv   = (const float*)d_in[6];
    const float* Wo   = (const float*)d_in[7];
    const float* bo   = (const float*)d_in[8];
    const float* proj = (const float*)d_in[9];
    float* out = (float*)d_out;

    const int FEAT_SMEM = 20480 + 40960 + 4 * 128 * 4;   // 63488
    cudaFuncSetAttribute(feat_mma<0>, cudaFuncAttributeMaxDynamicSharedMemorySize, FEAT_SMEM);
    cudaFuncSetAttribute(feat_mma<1>, cudaFuncAttributeMaxDynamicSharedMemorySize, FEAT_SMEM);

    // input splits (bias first so ncu -s 5 samples the QKV GEMM)
    bias_cat_kernel<<<3, DD>>>(bq, bk, bv);
    split_wqkv_kernel<<<dim3(DD * DD / 1024, 3), 256>>>(Wq, Wk, Wv);
    split_wo_kernel<<<DD * DD / 1024, 256>>>(Wo);
    split_proj_kernel<<<MF * DH / 1024, 256>>>(proj);
    split_x_kernel<<<TT * DD / 1024, 256>>>(x);

    // QKV projection -> q/k/v hi/lo bf16 head layout
    mma_gemm<0, 768><<<dim3(3 * DD / 128, TT / 128), 256>>>(nullptr, nullptr);

    diag_kernel<<<dim3(RR / 8, 2), 256>>>();

    // feature GEMMs: k stores raw xp + rowmax; q fuses rowmax+exp -> phi split
    feat_mma<0><<<RR / 128, 512, FEAT_SMEM>>>();
    feat_mma<1><<<RR / 128, 512, FEAT_SMEM>>>();

    kheadmax_kernel<<<NBH, 256>>>();
    kexp_kernel<<<dim3(NN / 256, NBH), 256>>>();

    // ctx = kp^T @ v  -> ctx hi/lo
    ctx_mma<<<dim3(2, NBH), 256>>>();

    dden_kernel<<<RR / 8, 256>>>();

    // out_attn = (qp @ ctx) * dinv -> attn hi/lo token layout
    outattn_mma<<<RR / 128, 256>>>();

    // output projection
    mma_gemm<1, 768><<<dim3(DD / 128, TT / 128), 256>>>(bo, out);
}